// round 5
// baseline (speedup 1.0000x reference)
#include <cuda_runtime.h>

#define L_ 50
#define T_ 100
#define D_ 64
#define I_MAX 100000
#define B_MAX 8192
#define WPAD 66   // even pad: b64 row reads aligned + conflict-free; transpose STS 2-way only

typedef unsigned long long ull;

// Precomputed scratch (static __device__ arrays — allowed)
__device__ float g_PE[I_MAX * 128];     // interleaved per 4: {P[2d],P[2d+1],E[2d],E[2d+1]}
__device__ float g_ufg[B_MAX * D_];     // per-user gate bias (incl. both biases)
__device__ float g_t2[B_MAX * L_];      // user_emb @ inst_gate_user

__device__ __forceinline__ ull ffma2(ull a, ull b, ull c) {
    ull d;
    asm("fma.rn.f32x2 %0, %1, %2, %3;" : "=l"(d) : "l"(a), "l"(b), "l"(c));
    return d;
}
__device__ __forceinline__ ull dup2(float x) {
    ull r;
    asm("mov.b64 %0, {%1, %1};" : "=l"(r) : "f"(x));
    return r;
}
__device__ __forceinline__ float2 unpack2(ull v) {
    float2 f;
    asm("mov.b64 {%0, %1}, %2;" : "=f"(f.x), "=f"(f.y) : "l"(v));
    return f;
}
__device__ __forceinline__ float sigf(float x) {
    return __fdividef(1.0f, 1.0f + __expf(-x));
}

// ---------------- Kernel 1: g_PE = [item_table @ fg_item_W.T | item_table] ----------------
// 32 rows/CTA, 256 threads, FFMA2 packed math. E staged as duplicated (e,e) b64 pairs.
__global__ __launch_bounds__(256) void k_precompute_P(
    const float* __restrict__ item_table,
    const float* __restrict__ fg_item_W,
    int R)
{
    __shared__ ull   Ed8[32 * 64];       // Ed8[r][k] = (e,e)  16KB
    __shared__ float Wt[64 * WPAD];      // Wt[k][d] = W[d][k] 16.9KB

    const int tid = threadIdx.x, warp = tid >> 5, lane = tid & 31;
    const int d0 = lane << 1;
    const int r0 = blockIdx.x * 32;

    #pragma unroll
    for (int e = tid; e < 4096; e += 256) {
        int d = e >> 6, k = e & 63;
        Wt[k * WPAD + d] = fg_item_W[e];          // coalesced LDG, 2-way STS
    }
    const float4* it4 = (const float4*)item_table;
    #pragma unroll
    for (int i = tid; i < 512; i += 256) {        // 32 rows x 16 float4
        int rl = i >> 4, c = i & 15;
        int r = r0 + rl; if (r >= R) r = R - 1;
        float4 v = it4[r * 16 + c];
        int base = (rl << 6) + (c << 2);
        Ed8[base]     = dup2(v.x);
        Ed8[base + 1] = dup2(v.y);
        Ed8[base + 2] = dup2(v.z);
        Ed8[base + 3] = dup2(v.w);
    }
    __syncthreads();

    const int rb = warp << 2;                     // 4 rows per warp
    ull acc[4];
    #pragma unroll
    for (int j = 0; j < 4; j++) acc[j] = 0ull;

    const ull* Wt8 = (const ull*)Wt;              // row k at k*33 (b64 units)
    #pragma unroll
    for (int k = 0; k < 64; k += 2) {
        ull w0 = Wt8[k * 33 + lane];              // (W[d0][k], W[d0+1][k])
        ull w1 = Wt8[(k + 1) * 33 + lane];
        #pragma unroll
        for (int j = 0; j < 4; j++) {
            ulonglong2 ee = *(const ulonglong2*)&Ed8[((rb + j) << 6) + k];  // broadcast
            acc[j] = ffma2(ee.x, w0, acc[j]);
            acc[j] = ffma2(ee.y, w1, acc[j]);
        }
    }
    #pragma unroll
    for (int j = 0; j < 4; j++) {
        int r = r0 + rb + j;
        if (r < R) {
            float2 p = unpack2(acc[j]);
            float ex = unpack2(Ed8[((rb + j) << 6) + d0]).x;
            float ey = unpack2(Ed8[((rb + j) << 6) + d0 + 1]).x;
            *(float4*)&g_PE[r * 128 + (lane << 2)] = make_float4(p.x, p.y, ex, ey);
        }
    }
}

// ---------------- Kernel 2: per-user ufg and t2 (8 users/CTA) ----------------
__global__ __launch_bounds__(256) void k_user(
    const int* __restrict__ user_ids,
    const float* __restrict__ user_table,
    const float* __restrict__ fg_user_W,
    const float* __restrict__ fg_item_b,
    const float* __restrict__ fg_user_b,
    const float* __restrict__ inst_gate_user,
    int B)
{
    __shared__ float Wt[64 * WPAD];
    __shared__ float IG[64 * L_];
    __shared__ float UE[8 * 64];
    __shared__ float bs[64];
    __shared__ int   uids[8];

    const int tid = threadIdx.x;
    #pragma unroll
    for (int e = tid; e < 4096; e += 256) {
        int d = e >> 6, k = e & 63;
        Wt[k * WPAD + d] = fg_user_W[e];
    }
    for (int e = tid; e < 64 * L_; e += 256) IG[e] = inst_gate_user[e];
    if (tid < 64) bs[tid] = fg_item_b[tid] + fg_user_b[tid];
    const int u0 = blockIdx.x * 8;
    if (tid < 8) {
        int u = u0 + tid;
        uids[tid] = (u < B) ? user_ids[u] : user_ids[0];
    }
    __syncthreads();
    const float4* ut4 = (const float4*)user_table;
    if (tid < 128)
        ((float4*)UE)[tid] = ut4[uids[tid >> 4] * 16 + (tid & 15)];
    __syncthreads();

    const int d = tid & 63, ug = tid >> 6;
    #pragma unroll
    for (int uu = ug; uu < 8; uu += 4) {
        float acc = bs[d];
        #pragma unroll
        for (int k = 0; k < 64; k++)
            acc = fmaf(UE[uu * 64 + k], Wt[k * WPAD + d], acc);
        int u = u0 + uu;
        if (u < B) g_ufg[u * 64 + d] = acc;
    }
    for (int idx = tid; idx < 8 * L_; idx += 256) {
        int uu = idx / L_, l = idx - uu * L_;
        float acc = 0.f;
        #pragma unroll
        for (int k = 0; k < 64; k++)
            acc = fmaf(UE[uu * 64 + k], IG[k * L_ + l], acc);
        int u = u0 + uu;
        if (u < B) g_t2[u * L_ + l] = acc;
    }
}

// ---------------- Kernel 3: main (1 gather per l via g_PE, 128 threads) ----------------
__global__ __launch_bounds__(128) void k_main(
    const int* __restrict__ user_ids,
    const int* __restrict__ item_seq_ids,
    const int* __restrict__ target_item_ids,
    const float* __restrict__ user_table,
    const float* __restrict__ W2_table,
    const float* __restrict__ b2_table,
    const float* __restrict__ inst_gate_item,
    float* __restrict__ out)
{
    __shared__ int   sid[L_ + 2];
    __shared__ float uf[64], t2s[L_ + 2];
    __shared__ float UN[4 * 64], SI[4 * 64], IS[4];
    __shared__ float v[64];
    __shared__ float s_is;

    const int b = blockIdx.x;
    const int tid = threadIdx.x, warp = tid >> 5, lane = tid & 31, d0 = lane << 1;

    if (tid < L_) {
        sid[tid] = item_seq_ids[b * L_ + tid];
        t2s[tid] = g_t2[b * L_ + tid];
    } else if (tid >= 64) {
        uf[tid - 64] = g_ufg[b * 64 + (tid - 64)];
    }
    __syncthreads();

    const float2 gi = *(const float2*)&inst_gate_item[d0];
    const float ufx = uf[d0], ufy = uf[d0 + 1];
    float unx = 0.f, uny = 0.f, six = 0.f, siy = 0.f, isum = 0.f;

    #pragma unroll
    for (int j = 0; j < 13; j++) {
        int l = warp + (j << 2);
        if (l < L_) {
            int id = sid[l];
            float4 pe = *(const float4*)&g_PE[id * 128 + (lane << 2)];  // 1 LDG.128 per l
            float gx = sigf(pe.x + ufx) * pe.z;
            float gy = sigf(pe.y + ufy) * pe.w;
            float t1 = gx * gi.x + gy * gi.y;
            #pragma unroll
            for (int off = 16; off; off >>= 1)
                t1 += __shfl_xor_sync(0xffffffffu, t1, off);
            float inst = sigf(t1 + t2s[l]);
            unx = fmaf(gx, inst, unx);
            uny = fmaf(gy, inst, uny);
            six += pe.z;  siy += pe.w;  isum += inst;
        }
    }
    *(float2*)&UN[warp * 64 + d0] = make_float2(unx, uny);
    *(float2*)&SI[warp * 64 + d0] = make_float2(six, siy);
    if (lane == 0) IS[warp] = isum;
    __syncthreads();

    if (tid < 64) {
        float a = UN[tid] + UN[64 + tid] + UN[128 + tid] + UN[192 + tid];
        float s = SI[tid] + SI[64 + tid] + SI[128 + tid] + SI[192 + tid];
        UN[tid] = a;  SI[tid] = s;
        if (tid == 0) s_is = IS[0] + IS[1] + IS[2] + IS[3];
    }
    __syncthreads();
    if (tid < 64) {
        int uid = user_ids[b];
        v[tid] = user_table[uid * 64 + tid] + __fdividef(UN[tid], s_is) + SI[tid];
    }
    __syncthreads();

    const float vx = v[d0], vy = v[d0 + 1];
    #pragma unroll
    for (int j = 0; j < 25; j++) {
        int t = warp + (j << 2);                    // always < 100
        int id = target_item_ids[b * T_ + t];
        float2 w = *(const float2*)&W2_table[id * 64 + d0];
        float bb = __ldg(&b2_table[id]);
        float p = w.x * vx + w.y * vy;
        #pragma unroll
        for (int off = 16; off; off >>= 1)
            p += __shfl_xor_sync(0xffffffffu, p, off);
        if (lane == 0) out[b * T_ + t] = p + bb;
    }
}

extern "C" void kernel_launch(void* const* d_in, const int* in_sizes, int n_in,
                              void* d_out, int out_size) {
    const int B = in_sizes[0] > B_MAX ? B_MAX : in_sizes[0];
    int R = in_sizes[4] / D_;
    if (R > I_MAX) R = I_MAX;

    k_user<<<(B + 7) / 8, 256>>>(
        (const int*)d_in[0], (const float*)d_in[3], (const float*)d_in[9],
        (const float*)d_in[8], (const float*)d_in[10], (const float*)d_in[12], B);

    k_precompute_P<<<(R + 31) / 32, 256>>>(
        (const float*)d_in[4], (const float*)d_in[7], R);

    k_main<<<B, 128>>>(
        (const int*)d_in[0], (const int*)d_in[1], (const int*)d_in[2],
        (const float*)d_in[3], (const float*)d_in[5], (const float*)d_in[6],
        (const float*)d_in[11], (float*)d_out);
}

// round 6
// speedup vs baseline: 1.1736x; 1.1736x over previous
#include <cuda_runtime.h>

#define L_ 50
#define T_ 100
#define D_ 64
#define I_MAX 100000
#define B_MAX 8192
#define WPAD 66   // even pad: b64 row reads aligned + conflict-free

typedef unsigned long long ull;

__device__ float g_P[I_MAX * D_];       // item_table @ fg_item_W.T
__device__ float g_ufg[B_MAX * D_];     // per-user gate bias (incl. both biases)
__device__ float g_t2[B_MAX * L_];      // user_emb @ inst_gate_user

__device__ __forceinline__ ull ffma2(ull a, ull b, ull c) {
    ull d;
    asm("fma.rn.f32x2 %0, %1, %2, %3;" : "=l"(d) : "l"(a), "l"(b), "l"(c));
    return d;
}
__device__ __forceinline__ ull dup2(float x) {
    ull r;
    asm("mov.b64 %0, {%1, %1};" : "=l"(r) : "f"(x));
    return r;
}
__device__ __forceinline__ float sigf(float x) {
    return __fdividef(1.0f, 1.0f + __expf(-x));
}

// ---------------- Kernel 1: g_P = item_table @ fg_item_W.T ----------------
// 128 threads, 32 rows/CTA, 8 rows/warp, FFMA2 packed math.
__global__ __launch_bounds__(128) void k_precompute_P(
    const float* __restrict__ item_table,
    const float* __restrict__ fg_item_W,
    int R)
{
    __shared__ ull   Ed8[32 * 64];       // Ed8[r][k] = (e,e)  16KB
    __shared__ float Wt[64 * WPAD];      // Wt[k][d] = W[d][k] 16.9KB

    const int tid = threadIdx.x, warp = tid >> 5, lane = tid & 31;
    const int r0 = blockIdx.x * 32;

    #pragma unroll
    for (int e = tid; e < 4096; e += 128) {
        int d = e >> 6, k = e & 63;
        Wt[k * WPAD + d] = fg_item_W[e];          // coalesced LDG, transposed STS
    }
    const float4* it4 = (const float4*)item_table;
    #pragma unroll
    for (int i = tid; i < 512; i += 128) {        // 32 rows x 16 float4
        int rl = i >> 4, c = i & 15;
        int r = r0 + rl; if (r >= R) r = R - 1;
        float4 v = it4[r * 16 + c];
        int base = (rl << 6) + (c << 2);
        Ed8[base]     = dup2(v.x);
        Ed8[base + 1] = dup2(v.y);
        Ed8[base + 2] = dup2(v.z);
        Ed8[base + 3] = dup2(v.w);
    }
    __syncthreads();

    const int rb = warp << 3;                     // 8 rows per warp
    ull acc[8];
    #pragma unroll
    for (int j = 0; j < 8; j++) acc[j] = 0ull;

    const ull* Wt8 = (const ull*)Wt;              // row k at k*33 (b64 units)
    #pragma unroll 8
    for (int k = 0; k < 64; k += 2) {
        ull w0 = Wt8[k * 33 + lane];              // (W[d0][k], W[d0+1][k])
        ull w1 = Wt8[(k + 1) * 33 + lane];
        #pragma unroll
        for (int j = 0; j < 8; j++) {
            ulonglong2 ee = *(const ulonglong2*)&Ed8[((rb + j) << 6) + k];  // broadcast
            acc[j] = ffma2(ee.x, w0, acc[j]);
            acc[j] = ffma2(ee.y, w1, acc[j]);
        }
    }
    ull* P8 = (ull*)g_P;
    #pragma unroll
    for (int j = 0; j < 8; j++) {
        int r = r0 + rb + j;
        if (r < R) P8[r * 32 + lane] = acc[j];
    }
}

// ---------------- Kernel 2: per-user ufg and t2 (32 users/CTA) ----------------
__global__ __launch_bounds__(256) void k_user(
    const int* __restrict__ user_ids,
    const float* __restrict__ user_table,
    const float* __restrict__ fg_user_W,
    const float* __restrict__ fg_item_b,
    const float* __restrict__ fg_user_b,
    const float* __restrict__ inst_gate_user,
    int B)
{
    __shared__ float Wt[64 * WPAD];
    __shared__ float IG[64 * L_];
    __shared__ float UE[32 * 64];
    __shared__ float bs[64];
    __shared__ int   uids[32];

    const int tid = threadIdx.x;
    #pragma unroll
    for (int e = tid; e < 4096; e += 256) {
        int d = e >> 6, k = e & 63;
        Wt[k * WPAD + d] = fg_user_W[e];
    }
    for (int e = tid; e < 64 * L_; e += 256) IG[e] = inst_gate_user[e];
    if (tid < 64) bs[tid] = fg_item_b[tid] + fg_user_b[tid];
    const int u0 = blockIdx.x * 32;
    if (tid < 32) {
        int u = u0 + tid;
        uids[tid] = (u < B) ? user_ids[u] : user_ids[0];
    }
    __syncthreads();
    const float4* ut4 = (const float4*)user_table;
    #pragma unroll
    for (int i = tid; i < 512; i += 256)
        ((float4*)UE)[i] = ut4[uids[i >> 4] * 16 + (i & 15)];
    __syncthreads();

    const int d = tid & 63, ug = tid >> 6;
    #pragma unroll
    for (int uu = ug; uu < 32; uu += 4) {
        float acc = bs[d];
        #pragma unroll
        for (int k = 0; k < 64; k++)
            acc = fmaf(UE[uu * 64 + k], Wt[k * WPAD + d], acc);
        int u = u0 + uu;
        if (u < B) g_ufg[u * 64 + d] = acc;
    }
    for (int idx = tid; idx < 32 * L_; idx += 256) {
        int uu = idx / L_, l = idx - uu * L_;
        float acc = 0.f;
        #pragma unroll
        for (int k = 0; k < 64; k++)
            acc = fmaf(UE[uu * 64 + k], IG[k * L_ + l], acc);
        int u = u0 + uu;
        if (u < B) g_t2[u * L_ + l] = acc;
    }
}

// ---------------- Kernel 3: main — half-warp per row, 4-level shfl, hoisted gathers --------
__global__ __launch_bounds__(128) void k_main(
    const int* __restrict__ user_ids,
    const int* __restrict__ item_seq_ids,
    const int* __restrict__ target_item_ids,
    const float* __restrict__ user_table,
    const float* __restrict__ item_table,
    const float* __restrict__ W2_table,
    const float* __restrict__ b2_table,
    const float* __restrict__ inst_gate_item,
    float* __restrict__ out)
{
    __shared__ int   sid[56];            // padded + clamped
    __shared__ float t2s[56];
    __shared__ float uf[64];
    __shared__ float RU[8 * 64], RS[8 * 64], IS[8];
    __shared__ float v[64];
    __shared__ float s_is;

    const int b = blockIdx.x;
    const int tid = threadIdx.x;
    const int hw = tid >> 4;             // half-warp 0..7
    const int hl = tid & 15;
    const int d4 = hl << 2;              // dims d4..d4+3

    if (tid < 56) {
        int l = tid < L_ ? tid : (L_ - 1);
        sid[tid] = item_seq_ids[b * L_ + l];
        t2s[tid] = g_t2[b * L_ + l];
    } else if (tid >= 64) {
        uf[tid - 64] = g_ufg[b * 64 + (tid - 64)];
    }
    __syncthreads();

    const float4 gi = *(const float4*)&inst_gate_item[d4];
    const float4 uf4 = *(const float4*)&uf[d4];

    // ---- l-phase: 7 rounds, row = hw + 8*j, all gathers hoisted ----
    int   ids[7];  float t2v[7];
    #pragma unroll
    for (int j = 0; j < 7; j++) { int l = hw + (j << 3); ids[j] = sid[l]; t2v[j] = t2s[l]; }
    float4 p[7], e[7];
    #pragma unroll
    for (int j = 0; j < 7; j++) p[j] = *(const float4*)&g_P[ids[j] * 64 + d4];
    #pragma unroll
    for (int j = 0; j < 7; j++) e[j] = *(const float4*)&item_table[ids[j] * 64 + d4];

    float4 un = make_float4(0.f, 0.f, 0.f, 0.f);
    float4 si = make_float4(0.f, 0.f, 0.f, 0.f);
    float  isum = 0.f;
    #pragma unroll
    for (int j = 0; j < 7; j++) {
        int l = hw + (j << 3);
        float valid = (l < L_) ? 1.f : 0.f;
        float gx = sigf(p[j].x + uf4.x) * e[j].x;
        float gy = sigf(p[j].y + uf4.y) * e[j].y;
        float gz = sigf(p[j].z + uf4.z) * e[j].z;
        float gw = sigf(p[j].w + uf4.w) * e[j].w;
        float t1 = gx * gi.x + gy * gi.y + gz * gi.z + gw * gi.w;
        #pragma unroll
        for (int off = 8; off; off >>= 1)
            t1 += __shfl_xor_sync(0xffffffffu, t1, off);   // 4-level, within half-warp
        float inst = sigf(t1 + t2v[j]) * valid;
        un.x = fmaf(gx, inst, un.x); un.y = fmaf(gy, inst, un.y);
        un.z = fmaf(gz, inst, un.z); un.w = fmaf(gw, inst, un.w);
        si.x = fmaf(e[j].x, valid, si.x); si.y = fmaf(e[j].y, valid, si.y);
        si.z = fmaf(e[j].z, valid, si.z); si.w = fmaf(e[j].w, valid, si.w);
        isum += inst;
    }
    *(float4*)&RU[hw * 64 + d4] = un;
    *(float4*)&RS[hw * 64 + d4] = si;
    if (hl == 0) IS[hw] = isum;
    __syncthreads();

    if (tid < 64) {
        float a = 0.f, s = 0.f;
        #pragma unroll
        for (int w = 0; w < 8; w++) { a += RU[w * 64 + tid]; s += RS[w * 64 + tid]; }
        if (tid == 0)
            s_is = IS[0] + IS[1] + IS[2] + IS[3] + IS[4] + IS[5] + IS[6] + IS[7];
        RU[tid] = a; RS[tid] = s;
    }
    __syncthreads();
    if (tid < 64) {
        int uid = user_ids[b];
        v[tid] = user_table[uid * 64 + tid] + __fdividef(RU[tid], s_is) + RS[tid];
    }
    __syncthreads();

    // ---- t-phase: 13 rounds, t = hw + 8*j, hoisted in two chunks ----
    const float4 v4 = *(const float4*)&v[d4];
    const int* tids = target_item_ids + b * T_;

    #pragma unroll
    for (int c = 0; c < 2; c++) {
        const int j0 = c ? 7 : 0, nj = c ? 6 : 7;
        int   wid_[7]; float b2v[7]; float4 w4[7];
        #pragma unroll
        for (int j = 0; j < 7; j++) {
            if (j < nj) {
                int t = hw + ((j0 + j) << 3);
                if (t >= T_) t = T_ - 1;
                wid_[j] = tids[t];
            }
        }
        #pragma unroll
        for (int j = 0; j < 7; j++)
            if (j < nj) w4[j] = *(const float4*)&W2_table[wid_[j] * 64 + d4];
        #pragma unroll
        for (int j = 0; j < 7; j++)
            if (j < nj) b2v[j] = __ldg(&b2_table[wid_[j]]);
        #pragma unroll
        for (int j = 0; j < 7; j++) {
            if (j < nj) {
                float pp = w4[j].x * v4.x + w4[j].y * v4.y + w4[j].z * v4.z + w4[j].w * v4.w;
                #pragma unroll
                for (int off = 8; off; off >>= 1)
                    pp += __shfl_xor_sync(0xffffffffu, pp, off);
                int t = hw + ((j0 + j) << 3);
                if (hl == 0 && t < T_) out[b * T_ + t] = pp + b2v[j];
            }
        }
    }
}

extern "C" void kernel_launch(void* const* d_in, const int* in_sizes, int n_in,
                              void* d_out, int out_size) {
    const int B = in_sizes[0] > B_MAX ? B_MAX : in_sizes[0];
    int R = in_sizes[4] / D_;
    if (R > I_MAX) R = I_MAX;

    k_user<<<(B + 31) / 32, 256>>>(
        (const int*)d_in[0], (const float*)d_in[3], (const float*)d_in[9],
        (const float*)d_in[8], (const float*)d_in[10], (const float*)d_in[12], B);

    k_precompute_P<<<(R + 31) / 32, 128>>>(
        (const float*)d_in[4], (const float*)d_in[7], R);

    k_main<<<B, 128>>>(
        (const int*)d_in[0], (const int*)d_in[1], (const int*)d_in[2],
        (const float*)d_in[3], (const float*)d_in[4], (const float*)d_in[5],
        (const float*)d_in[6], (const float*)d_in[11], (float*)d_out);
}

// round 7
// speedup vs baseline: 1.3529x; 1.1528x over previous
#include <cuda_runtime.h>

#define L_ 50
#define T_ 100
#define D_ 64
#define I_MAX 100000
#define B_MAX 8192
#define WPAD 66    // even pad: b64 row reads aligned + conflict-free
#define WCP 116    // combined user-weight pad (64 ufg cols + 50 t2 cols + 2 pad), even

typedef unsigned long long ull;

__device__ float g_P[I_MAX * D_];       // item_table @ fg_item_W.T
__device__ float g_ufg[B_MAX * D_];     // per-user gate bias (incl. both biases)
__device__ float g_t2[B_MAX * L_];      // user_emb @ inst_gate_user

__device__ __forceinline__ ull ffma2(ull a, ull b, ull c) {
    ull d;
    asm("fma.rn.f32x2 %0, %1, %2, %3;" : "=l"(d) : "l"(a), "l"(b), "l"(c));
    return d;
}
__device__ __forceinline__ ull dup2(float x) {
    ull r;
    asm("mov.b64 %0, {%1, %1};" : "=l"(r) : "f"(x));
    return r;
}
__device__ __forceinline__ float sigf(float x) {
    return __fdividef(1.0f, 1.0f + __expf(-x));
}

// ---------------- Fused precompute: P-GEMM CTAs + user-GEMV CTAs in one grid ----------------
struct SmemP { ull Ed8[32 * 64]; float Wt[64 * WPAD]; };                  // ~32.9 KB
struct SmemU { float Wc[64 * WCP]; ull UEd8[16 * 64]; float bs[64]; int uids[16]; }; // ~38 KB
union SmemPre { SmemP p; SmemU u; };

__global__ __launch_bounds__(128) void k_pre(
    const float* __restrict__ item_table,
    const float* __restrict__ fg_item_W,
    const int*   __restrict__ user_ids,
    const float* __restrict__ user_table,
    const float* __restrict__ fg_user_W,
    const float* __restrict__ fg_item_b,
    const float* __restrict__ fg_user_b,
    const float* __restrict__ inst_gate_user,
    int R, int B, int nP)
{
    __shared__ SmemPre s;
    const int tid = threadIdx.x, warp = tid >> 5, lane = tid & 31;

    if ((int)blockIdx.x < nP) {
        // ---------- P branch: g_P[r] = item_table[r] @ fg_item_W.T (FFMA2) ----------
        const int r0 = blockIdx.x * 32;
        #pragma unroll
        for (int e = tid; e < 4096; e += 128) {
            int d = e >> 6, k = e & 63;
            s.p.Wt[k * WPAD + d] = fg_item_W[e];
        }
        const float4* it4 = (const float4*)item_table;
        #pragma unroll
        for (int i = tid; i < 512; i += 128) {
            int rl = i >> 4, c = i & 15;
            int r = r0 + rl; if (r >= R) r = R - 1;
            float4 v = it4[r * 16 + c];
            int base = (rl << 6) + (c << 2);
            s.p.Ed8[base]     = dup2(v.x);
            s.p.Ed8[base + 1] = dup2(v.y);
            s.p.Ed8[base + 2] = dup2(v.z);
            s.p.Ed8[base + 3] = dup2(v.w);
        }
        __syncthreads();

        const int rb = warp << 3;                 // 8 rows per warp
        ull acc[8];
        #pragma unroll
        for (int j = 0; j < 8; j++) acc[j] = 0ull;
        const ull* Wt8 = (const ull*)s.p.Wt;      // row k at k*33 (b64 units)
        #pragma unroll 8
        for (int k = 0; k < 64; k += 2) {
            ull w0 = Wt8[k * 33 + lane];
            ull w1 = Wt8[(k + 1) * 33 + lane];
            #pragma unroll
            for (int j = 0; j < 8; j++) {
                ulonglong2 ee = *(const ulonglong2*)&s.p.Ed8[((rb + j) << 6) + k];
                acc[j] = ffma2(ee.x, w0, acc[j]);
                acc[j] = ffma2(ee.y, w1, acc[j]);
            }
        }
        ull* P8 = (ull*)g_P;
        #pragma unroll
        for (int j = 0; j < 8; j++) {
            int r = r0 + rb + j;
            if (r < R) P8[r * 32 + lane] = acc[j];
        }
    } else {
        // ---------- User branch: ufg + t2 for 16 users (FFMA2) ----------
        const int u0c = (blockIdx.x - nP) * 16;
        #pragma unroll
        for (int e = tid; e < 4096; e += 128) {   // transpose fg_user_W -> cols 0..63
            int d = e >> 6, k = e & 63;
            s.u.Wc[k * WCP + d] = fg_user_W[e];
        }
        for (int e = tid; e < 64 * L_; e += 128) { // copy inst_gate_user -> cols 64..113
            int k = e / L_, l = e - k * L_;
            s.u.Wc[k * WCP + 64 + l] = inst_gate_user[e];
        }
        if (tid < 64) s.u.bs[tid] = fg_item_b[tid] + fg_user_b[tid];
        if (tid < 16) {
            int u = u0c + tid;
            s.u.uids[tid] = user_ids[u < B ? u : (B - 1)];
        }
        __syncthreads();
        const float4* ut4 = (const float4*)user_table;
        #pragma unroll
        for (int i = tid; i < 256; i += 128) {    // 16 users x 16 float4
            int uu = i >> 4, c4 = i & 15;
            float4 v = ut4[s.u.uids[uu] * 16 + c4];
            int base = (uu << 6) + (c4 << 2);
            s.u.UEd8[base]     = dup2(v.x);
            s.u.UEd8[base + 1] = dup2(v.y);
            s.u.UEd8[base + 2] = dup2(v.z);
            s.u.UEd8[base + 3] = dup2(v.w);
        }
        __syncthreads();

        if (warp < 2) {
            // ufg: warp covers all 64 cols (b64 pairs), 8 users
            const int ub = warp << 3;
            ull acc[8];
            ull binit = *(const ull*)&s.u.bs[lane << 1];
            #pragma unroll
            for (int j = 0; j < 8; j++) acc[j] = binit;
            #pragma unroll 8
            for (int k = 0; k < 64; k++) {
                ull w = *(const ull*)&s.u.Wc[k * WCP + (lane << 1)];
                #pragma unroll
                for (int j = 0; j < 8; j++)
                    acc[j] = ffma2(s.u.UEd8[((ub + j) << 6) + k], w, acc[j]);
            }
            #pragma unroll
            for (int j = 0; j < 8; j++) {
                int u = u0c + ub + j;
                if (u < B) ((ull*)g_ufg)[u * 32 + lane] = acc[j];
            }
        } else if (lane < 25) {
            // t2: lanes 0..24 cover 50 cols (b64 pairs), 8 users
            const int ub = (warp - 2) << 3;
            ull acc[8];
            #pragma unroll
            for (int j = 0; j < 8; j++) acc[j] = 0ull;
            #pragma unroll 8
            for (int k = 0; k < 64; k++) {
                ull w = *(const ull*)&s.u.Wc[k * WCP + 64 + (lane << 1)];
                #pragma unroll
                for (int j = 0; j < 8; j++)
                    acc[j] = ffma2(s.u.UEd8[((ub + j) << 6) + k], w, acc[j]);
            }
            #pragma unroll
            for (int j = 0; j < 8; j++) {
                int u = u0c + ub + j;
                if (u < B) *(ull*)&g_t2[u * L_ + (lane << 1)] = acc[j];
            }
        }
    }
}

// ---------------- Main: half-warp per row, 4-level shfl, hoisted gathers ----------------
__global__ __launch_bounds__(128) void k_main(
    const int* __restrict__ user_ids,
    const int* __restrict__ item_seq_ids,
    const int* __restrict__ target_item_ids,
    const float* __restrict__ user_table,
    const float* __restrict__ item_table,
    const float* __restrict__ W2_table,
    const float* __restrict__ b2_table,
    const float* __restrict__ inst_gate_item,
    float* __restrict__ out)
{
    __shared__ int   sid[56];
    __shared__ float t2s[56];
    __shared__ float uf[64];
    __shared__ float RU[8 * 64], RS[8 * 64], IS[8];
    __shared__ float v[64];
    __shared__ float s_is;
    __shared__ float outS[104];

    const int b = blockIdx.x;
    const int tid = threadIdx.x;
    const int hw = tid >> 4;             // half-warp 0..7
    const int hl = tid & 15;
    const int d4 = hl << 2;

    if (tid < 56) {
        int l = tid < L_ ? tid : (L_ - 1);
        sid[tid] = item_seq_ids[b * L_ + l];
        t2s[tid] = g_t2[b * L_ + l];
    } else if (tid >= 64) {
        uf[tid - 64] = g_ufg[b * 64 + (tid - 64)];
    }
    __syncthreads();

    const float4 gi = *(const float4*)&inst_gate_item[d4];
    const float4 uf4 = *(const float4*)&uf[d4];

    // ---- l-phase: 7 rounds, row = hw + 8*j, gathers hoisted ----
    int   ids[7];  float t2v[7];
    #pragma unroll
    for (int j = 0; j < 7; j++) { int l = hw + (j << 3); ids[j] = sid[l]; t2v[j] = t2s[l]; }
    float4 p[7], e[7];
    #pragma unroll
    for (int j = 0; j < 7; j++) p[j] = *(const float4*)&g_P[ids[j] * 64 + d4];
    #pragma unroll
    for (int j = 0; j < 7; j++) e[j] = *(const float4*)&item_table[ids[j] * 64 + d4];

    float4 un = make_float4(0.f, 0.f, 0.f, 0.f);
    float4 si = make_float4(0.f, 0.f, 0.f, 0.f);
    float  isum = 0.f;
    #pragma unroll
    for (int j = 0; j < 7; j++) {
        int l = hw + (j << 3);
        float valid = (l < L_) ? 1.f : 0.f;
        float gx = sigf(p[j].x + uf4.x) * e[j].x;
        float gy = sigf(p[j].y + uf4.y) * e[j].y;
        float gz = sigf(p[j].z + uf4.z) * e[j].z;
        float gw = sigf(p[j].w + uf4.w) * e[j].w;
        float t1 = gx * gi.x + gy * gi.y + gz * gi.z + gw * gi.w;
        #pragma unroll
        for (int off = 8; off; off >>= 1)
            t1 += __shfl_xor_sync(0xffffffffu, t1, off);
        float inst = sigf(t1 + t2v[j]) * valid;
        un.x = fmaf(gx, inst, un.x); un.y = fmaf(gy, inst, un.y);
        un.z = fmaf(gz, inst, un.z); un.w = fmaf(gw, inst, un.w);
        si.x = fmaf(e[j].x, valid, si.x); si.y = fmaf(e[j].y, valid, si.y);
        si.z = fmaf(e[j].z, valid, si.z); si.w = fmaf(e[j].w, valid, si.w);
        isum += inst;
    }
    *(float4*)&RU[hw * 64 + d4] = un;
    *(float4*)&RS[hw * 64 + d4] = si;
    if (hl == 0) IS[hw] = isum;
    __syncthreads();

    if (tid < 64) {
        float a = 0.f, ss = 0.f;
        #pragma unroll
        for (int w = 0; w < 8; w++) { a += RU[w * 64 + tid]; ss += RS[w * 64 + tid]; }
        if (tid == 0)
            s_is = IS[0] + IS[1] + IS[2] + IS[3] + IS[4] + IS[5] + IS[6] + IS[7];
        RU[tid] = a; RS[tid] = ss;
    }
    __syncthreads();
    if (tid < 64) {
        int uid = user_ids[b];
        v[tid] = user_table[uid * 64 + tid] + __fdividef(RU[tid], s_is) + RS[tid];
    }
    __syncthreads();

    // ---- t-phase: 13 rounds, staged output ----
    const float4 v4 = *(const float4*)&v[d4];
    const int* tids = target_item_ids + b * T_;

    #pragma unroll
    for (int c = 0; c < 2; c++) {
        const int j0 = c ? 7 : 0, nj = c ? 6 : 7;
        int   wid_[7]; float b2v[7]; float4 w4[7];
        #pragma unroll
        for (int j = 0; j < 7; j++) {
            if (j < nj) {
                int t = hw + ((j0 + j) << 3);
                if (t >= T_) t = T_ - 1;
                wid_[j] = tids[t];
            }
        }
        #pragma unroll
        for (int j = 0; j < 7; j++)
            if (j < nj) w4[j] = *(const float4*)&W2_table[wid_[j] * 64 + d4];
        #pragma unroll
        for (int j = 0; j < 7; j++)
            if (j < nj) b2v[j] = __ldg(&b2_table[wid_[j]]);
        #pragma unroll
        for (int j = 0; j < 7; j++) {
            if (j < nj) {
                float pp = w4[j].x * v4.x + w4[j].y * v4.y + w4[j].z * v4.z + w4[j].w * v4.w;
                #pragma unroll
                for (int off = 8; off; off >>= 1)
                    pp += __shfl_xor_sync(0xffffffffu, pp, off);
                int t = hw + ((j0 + j) << 3);
                if (hl == 0 && t < T_) outS[t] = pp + b2v[j];
            }
        }
    }
    __syncthreads();
    if (tid < T_) out[b * T_ + tid] = outS[tid];
}

extern "C" void kernel_launch(void* const* d_in, const int* in_sizes, int n_in,
                              void* d_out, int out_size) {
    const int B = in_sizes[0] > B_MAX ? B_MAX : in_sizes[0];
    int R = in_sizes[4] / D_;
    if (R > I_MAX) R = I_MAX;
    const int nP = (R + 31) / 32;
    const int nU = (B + 15) / 16;

    k_pre<<<nP + nU, 128>>>(
        (const float*)d_in[4], (const float*)d_in[7],
        (const int*)d_in[0], (const float*)d_in[3], (const float*)d_in[9],
        (const float*)d_in[8], (const float*)d_in[10], (const float*)d_in[12],
        R, B, nP);

    k_main<<<B, 128>>>(
        (const int*)d_in[0], (const int*)d_in[1], (const int*)d_in[2],
        (const float*)d_in[3], (const float*)d_in[4], (const float*)d_in[5],
        (const float*)d_in[6], (const float*)d_in[11], (float*)d_out);
}

// round 10
// speedup vs baseline: 1.3801x; 1.0201x over previous
#include <cuda_runtime.h>

#define L_ 50
#define T_ 100
#define D_ 64
#define I_MAX 100000
#define B_MAX 8192
#define WCP 116    // combined user-weight pad (64 ufg cols + 50 t2 cols + 2 pad), even

typedef unsigned long long ull;

__device__ float g_P[I_MAX * D_];       // item_table @ fg_item_W.T
__device__ float g_ufg[B_MAX * D_];     // per-user gate bias (incl. both biases)
__device__ float g_t2[B_MAX * L_];      // user_emb @ inst_gate_user

__device__ __forceinline__ ull ffma2(ull a, ull b, ull c) {
    ull d;
    asm("fma.rn.f32x2 %0, %1, %2, %3;" : "=l"(d) : "l"(a), "l"(b), "l"(c));
    return d;
}
__device__ __forceinline__ ull dup2(float x) {
    ull r;
    asm("mov.b64 %0, {%1, %1};" : "=l"(r) : "f"(x));
    return r;
}
__device__ __forceinline__ float sigf(float x) {
    return __fdividef(1.0f, 1.0f + __expf(-x));
}

// ---------------- Fused precompute: P-GEMM CTAs + user-GEMV CTAs ----------------
// P branch: 64 rows/CTA, 8 warps x 8 rows, FFMA2. W in XOR-swizzled stride-64 smem:
//   element (k,d) lives at b64 word  k*32 + ((d>>1) ^ (k&31)), float slot (d&1).
//   Stores (fixed d, k across lanes): 2-way conflict. Reads (lane ^ (k&31)): conflict-free.
struct SmemP { ull Ed8[64 * 64]; ull W8[64 * 32]; };                       // 32KB + 16KB = 48KB
struct SmemU { float Wc[64 * WCP]; ull UEd8[16 * 64]; float bs[64]; int uids[16]; }; // ~38 KB
union SmemPre { SmemP p; SmemU u; };

__global__ __launch_bounds__(256) void k_pre(
    const float* __restrict__ item_table,
    const float* __restrict__ fg_item_W,
    const int*   __restrict__ user_ids,
    const float* __restrict__ user_table,
    const float* __restrict__ fg_user_W,
    const float* __restrict__ fg_item_b,
    const float* __restrict__ fg_user_b,
    const float* __restrict__ inst_gate_user,
    int R, int B, int nP)
{
    __shared__ SmemPre s;
    const int tid = threadIdx.x, warp = tid >> 5, lane = tid & 31;

    if ((int)blockIdx.x < nP) {
        // ---------- P branch: g_P[r] = item_table[r] @ fg_item_W.T ----------
        const int r0 = blockIdx.x * 64;
        float* Wf = (float*)s.p.W8;
        #pragma unroll
        for (int e = tid; e < 4096; e += 256) {
            int d = e >> 6, k = e & 63;
            int word = k * 32 + ((d >> 1) ^ (k & 31));
            Wf[word * 2 + (d & 1)] = fg_item_W[e];
        }
        const float4* it4 = (const float4*)item_table;
        #pragma unroll
        for (int i = tid; i < 1024; i += 256) {       // 64 rows x 16 float4
            int rl = i >> 4, c = i & 15;
            int r = r0 + rl; if (r >= R) r = R - 1;
            float4 v = it4[r * 16 + c];
            int base = (rl << 6) + (c << 2);
            s.p.Ed8[base]     = dup2(v.x);
            s.p.Ed8[base + 1] = dup2(v.y);
            s.p.Ed8[base + 2] = dup2(v.z);
            s.p.Ed8[base + 3] = dup2(v.w);
        }
        __syncthreads();

        const int rb = warp << 3;                     // 8 rows per warp
        ull acc[8];
        #pragma unroll
        for (int j = 0; j < 8; j++) acc[j] = 0ull;
        #pragma unroll 8
        for (int k = 0; k < 64; k += 2) {
            ull w0 = s.p.W8[k * 32 + (lane ^ (k & 31))];
            ull w1 = s.p.W8[(k + 1) * 32 + (lane ^ ((k + 1) & 31))];
            #pragma unroll
            for (int j = 0; j < 8; j++) {
                ulonglong2 ee = *(const ulonglong2*)&s.p.Ed8[((rb + j) << 6) + k];
                acc[j] = ffma2(ee.x, w0, acc[j]);
                acc[j] = ffma2(ee.y, w1, acc[j]);
            }
        }
        ull* P8 = (ull*)g_P;
        #pragma unroll
        for (int j = 0; j < 8; j++) {
            int r = r0 + rb + j;
            if (r < R) P8[r * 32 + lane] = acc[j];
        }
    } else {
        // ---------- User branch: ufg + t2 for 16 users ----------
        const int u0c = (blockIdx.x - nP) * 16;
        #pragma unroll
        for (int e = tid; e < 4096; e += 256) {       // transpose fg_user_W -> cols 0..63
            int d = e >> 6, k = e & 63;
            s.u.Wc[k * WCP + d] = fg_user_W[e];
        }
        for (int e = tid; e < 64 * L_; e += 256) {    // inst_gate_user -> cols 64..113
            int k = e / L_, l = e - k * L_;
            s.u.Wc[k * WCP + 64 + l] = inst_gate_user[e];
        }
        if (tid < 64) s.u.bs[tid] = fg_item_b[tid] + fg_user_b[tid];
        if (tid < 16) {
            int u = u0c + tid;
            s.u.uids[tid] = user_ids[u < B ? u : (B - 1)];
        }
        __syncthreads();
        {
            const float4* ut4 = (const float4*)user_table;
            int uu = tid >> 4, c4 = tid & 15;         // 16 users x 16 float4 = 256 threads
            float4 v = ut4[s.u.uids[uu] * 16 + c4];
            int base = (uu << 6) + (c4 << 2);
            s.u.UEd8[base]     = dup2(v.x);
            s.u.UEd8[base + 1] = dup2(v.y);
            s.u.UEd8[base + 2] = dup2(v.z);
            s.u.UEd8[base + 3] = dup2(v.w);
        }
        __syncthreads();

        if (warp < 4) {
            // ufg: warps 0-3, 4 users each, lane covers 64 dims as b64 pairs
            const int ub = warp << 2;
            ull acc[4];
            ull binit = *(const ull*)&s.u.bs[lane << 1];
            #pragma unroll
            for (int j = 0; j < 4; j++) acc[j] = binit;
            #pragma unroll 8
            for (int k = 0; k < 64; k++) {
                ull w = *(const ull*)&s.u.Wc[k * WCP + (lane << 1)];
                #pragma unroll
                for (int j = 0; j < 4; j++)
                    acc[j] = ffma2(s.u.UEd8[((ub + j) << 6) + k], w, acc[j]);
            }
            #pragma unroll
            for (int j = 0; j < 4; j++) {
                int u = u0c + ub + j;
                if (u < B) ((ull*)g_ufg)[u * 32 + lane] = acc[j];
            }
        } else if (lane < 25) {
            // t2: warps 4-7, 4 users each, lanes 0..24 cover 50 cols as b64 pairs
            const int ub = (warp - 4) << 2;
            ull acc[4];
            #pragma unroll
            for (int j = 0; j < 4; j++) acc[j] = 0ull;
            #pragma unroll 8
            for (int k = 0; k < 64; k++) {
                ull w = *(const ull*)&s.u.Wc[k * WCP + 64 + (lane << 1)];
                #pragma unroll
                for (int j = 0; j < 4; j++)
                    acc[j] = ffma2(s.u.UEd8[((ub + j) << 6) + k], w, acc[j]);
            }
            #pragma unroll
            for (int j = 0; j < 4; j++) {
                int u = u0c + ub + j;
                if (u < B) *(ull*)&g_t2[u * L_ + (lane << 1)] = acc[j];
            }
        }
    }
}

// ---------------- Main: half-warp per row, 4-level shfl, hoisted gathers ----------------
__global__ __launch_bounds__(128, 14) void k_main(
    const int* __restrict__ user_ids,
    const int* __restrict__ item_seq_ids,
    const int* __restrict__ target_item_ids,
    const float* __restrict__ user_table,
    const float* __restrict__ item_table,
    const float* __restrict__ W2_table,
    const float* __restrict__ b2_table,
    const float* __restrict__ inst_gate_item,
    float* __restrict__ out)
{
    __shared__ int   sid[56];
    __shared__ float t2s[56];
    __shared__ float uf[64];
    __shared__ float RU[8 * 64], RS[8 * 64], IS[8];
    __shared__ float v[64];
    __shared__ float s_is;
    __shared__ float outS[104];

    const int b = blockIdx.x;
    const int tid = threadIdx.x;
    const int hw = tid >> 4;             // half-warp 0..7
    const int hl = tid & 15;
    const int d4 = hl << 2;

    if (tid < 56) {
        int l = tid < L_ ? tid : (L_ - 1);
        sid[tid] = item_seq_ids[b * L_ + l];
        t2s[tid] = g_t2[b * L_ + l];
    } else if (tid >= 64) {
        uf[tid - 64] = g_ufg[b * 64 + (tid - 64)];
    }
    __syncthreads();

    const float4 gi = *(const float4*)&inst_gate_item[d4];
    const float4 uf4 = *(const float4*)&uf[d4];

    // ---- l-phase: 7 rounds, row = hw + 8*j, gathers hoisted ----
    int   ids[7];  float t2v[7];
    #pragma unroll
    for (int j = 0; j < 7; j++) { int l = hw + (j << 3); ids[j] = sid[l]; t2v[j] = t2s[l]; }
    float4 p[7], e[7];
    #pragma unroll
    for (int j = 0; j < 7; j++) p[j] = *(const float4*)&g_P[ids[j] * 64 + d4];
    #pragma unroll
    for (int j = 0; j < 7; j++) e[j] = *(const float4*)&item_table[ids[j] * 64 + d4];

    float4 un = make_float4(0.f, 0.f, 0.f, 0.f);
    float4 si = make_float4(0.f, 0.f, 0.f, 0.f);
    float  isum = 0.f;
    #pragma unroll
    for (int j = 0; j < 7; j++) {
        int l = hw + (j << 3);
        float valid = (l < L_) ? 1.f : 0.f;
        float gx = sigf(p[j].x + uf4.x) * e[j].x;
        float gy = sigf(p[j].y + uf4.y) * e[j].y;
        float gz = sigf(p[j].z + uf4.z) * e[j].z;
        float gw = sigf(p[j].w + uf4.w) * e[j].w;
        float t1 = gx * gi.x + gy * gi.y + gz * gi.z + gw * gi.w;
        #pragma unroll
        for (int off = 8; off; off >>= 1)
            t1 += __shfl_xor_sync(0xffffffffu, t1, off);
        float inst = sigf(t1 + t2v[j]) * valid;
        un.x = fmaf(gx, inst, un.x); un.y = fmaf(gy, inst, un.y);
        un.z = fmaf(gz, inst, un.z); un.w = fmaf(gw, inst, un.w);
        si.x = fmaf(e[j].x, valid, si.x); si.y = fmaf(e[j].y, valid, si.y);
        si.z = fmaf(e[j].z, valid, si.z); si.w = fmaf(e[j].w, valid, si.w);
        isum += inst;
    }
    *(float4*)&RU[hw * 64 + d4] = un;
    *(float4*)&RS[hw * 64 + d4] = si;
    if (hl == 0) IS[hw] = isum;
    __syncthreads();

    if (tid < 64) {
        float a = 0.f, ss = 0.f;
        #pragma unroll
        for (int w = 0; w < 8; w++) { a += RU[w * 64 + tid]; ss += RS[w * 64 + tid]; }
        if (tid == 0)
            s_is = IS[0] + IS[1] + IS[2] + IS[3] + IS[4] + IS[5] + IS[6] + IS[7];
        RU[tid] = a; RS[tid] = ss;
    }
    __syncthreads();
    if (tid < 64) {
        int uid = user_ids[b];
        v[tid] = user_table[uid * 64 + tid] + __fdividef(RU[tid], s_is) + RS[tid];
    }
    __syncthreads();

    // ---- t-phase: 13 rounds in chunks {0..4, 5..8, 9..12}, staged output ----
    const float4 v4 = *(const float4*)&v[d4];
    const int* tids = target_item_ids + b * T_;

    #pragma unroll
    for (int c = 0; c < 3; c++) {
        const int j0 = (c == 0) ? 0 : (c == 1 ? 5 : 9);   // prefix sums of {5,4,4}
        const int nj = (c == 0) ? 5 : 4;
        int   wid_[5]; float b2v[5]; float4 w4[5];
        #pragma unroll
        for (int j = 0; j < 5; j++) {
            if (j < nj) {
                int t = hw + ((j0 + j) << 3);
                if (t >= T_) t = T_ - 1;
                wid_[j] = tids[t];
            }
        }
        #pragma unroll
        for (int j = 0; j < 5; j++)
            if (j < nj) w4[j] = *(const float4*)&W2_table[wid_[j] * 64 + d4];
        #pragma unroll
        for (int j = 0; j < 5; j++)
            if (j < nj) b2v[j] = __ldg(&b2_table[wid_[j]]);
        #pragma unroll
        for (int j = 0; j < 5; j++) {
            if (j < nj) {
                float pp = w4[j].x * v4.x + w4[j].y * v4.y + w4[j].z * v4.z + w4[j].w * v4.w;
                #pragma unroll
                for (int off = 8; off; off >>= 1)
                    pp += __shfl_xor_sync(0xffffffffu, pp, off);
                int t = hw + ((j0 + j) << 3);
                if (hl == 0 && t < T_) outS[t] = pp + b2v[j];
            }
        }
    }
    __syncthreads();
    if (tid < T_) out[b * T_ + tid] = outS[tid];
}

extern "C" void kernel_launch(void* const* d_in, const int* in_sizes, int n_in,
                              void* d_out, int out_size) {
    const int B = in_sizes[0] > B_MAX ? B_MAX : in_sizes[0];
    int R = in_sizes[4] / D_;
    if (R > I_MAX) R = I_MAX;
    const int nP = (R + 63) / 64;
    const int nU = (B + 15) / 16;

    k_pre<<<nP + nU, 256>>>(
        (const float*)d_in[4], (const float*)d_in[7],
        (const int*)d_in[0], (const float*)d_in[3], (const float*)d_in[9],
        (const float*)d_in[8], (const float*)d_in[10], (const float*)d_in[12],
        R, B, nP);

    k_main<<<B, 128>>>(
        (const int*)d_in[0], (const int*)d_in[1], (const int*)d_in[2],
        (const float*)d_in[3], (const float*)d_in[4], (const float*)d_in[5],
        (const float*)d_in[6], (const float*)d_in[11], (float*)d_out);
}

// round 11
// speedup vs baseline: 1.4822x; 1.0739x over previous
#include <cuda_runtime.h>
#include <cuda_bf16.h>

#define L_ 50
#define T_ 100
#define D_ 64
#define I_MAX 100000
#define B_MAX 8192
#define WCP 116

typedef unsigned long long ull;

__device__ __nv_bfloat16 g_P[I_MAX * D_];   // item_table @ fg_item_W.T  (bf16)
__device__ float g_ufg[B_MAX * D_];
__device__ float g_t2[B_MAX * L_];

__device__ __forceinline__ ull ffma2(ull a, ull b, ull c) {
    ull d;
    asm("fma.rn.f32x2 %0, %1, %2, %3;" : "=l"(d) : "l"(a), "l"(b), "l"(c));
    return d;
}
__device__ __forceinline__ ull dup2(float x) {
    ull r;
    asm("mov.b64 %0, {%1, %1};" : "=l"(r) : "f"(x));
    return r;
}
__device__ __forceinline__ float2 unpack2(ull v) {
    float2 f;
    asm("mov.b64 {%0, %1}, %2;" : "=f"(f.x), "=f"(f.y) : "l"(v));
    return f;
}
__device__ __forceinline__ float sigf(float x) {
    return __fdividef(1.0f, 1.0f + __expf(-x));
}

// ---------------- Fused precompute ----------------
// P branch: 64 rows/CTA, 4 warps x 16 rows, FFMA2. XOR-swizzled W (store word
// (d>>1)^(k&31), read word lane^(k&31)).
struct SmemP { ull Ed8[64 * 64]; ull W8[64 * 32]; };                        // 48KB
struct SmemU { float Wc[64 * WCP]; ull UEd8[16 * 64]; float bs[64]; int uids[16]; };
union SmemPre { SmemP p; SmemU u; };

__global__ __launch_bounds__(128) void k_pre(
    const float* __restrict__ item_table,
    const float* __restrict__ fg_item_W,
    const int*   __restrict__ user_ids,
    const float* __restrict__ user_table,
    const float* __restrict__ fg_user_W,
    const float* __restrict__ fg_item_b,
    const float* __restrict__ fg_user_b,
    const float* __restrict__ inst_gate_user,
    int R, int B, int nP)
{
    __shared__ SmemPre s;
    const int tid = threadIdx.x, warp = tid >> 5, lane = tid & 31;

    if ((int)blockIdx.x < nP) {
        const int r0 = blockIdx.x * 64;
        float* Wf = (float*)s.p.W8;
        #pragma unroll
        for (int e = tid; e < 4096; e += 128) {
            int d = e >> 6, k = e & 63;
            int word = k * 32 + ((d >> 1) ^ (k & 31));
            Wf[word * 2 + (d & 1)] = fg_item_W[e];
        }
        const float4* it4 = (const float4*)item_table;
        #pragma unroll
        for (int i = tid; i < 1024; i += 128) {
            int rl = i >> 4, c = i & 15;
            int r = r0 + rl; if (r >= R) r = R - 1;
            float4 v = it4[r * 16 + c];
            int base = (rl << 6) + (c << 2);
            s.p.Ed8[base]     = dup2(v.x);
            s.p.Ed8[base + 1] = dup2(v.y);
            s.p.Ed8[base + 2] = dup2(v.z);
            s.p.Ed8[base + 3] = dup2(v.w);
        }
        __syncthreads();

        const int rb = warp << 4;                     // 16 rows per warp
        ull acc[16];
        #pragma unroll
        for (int j = 0; j < 16; j++) acc[j] = 0ull;
        #pragma unroll 4
        for (int k = 0; k < 64; k += 2) {
            ull w0 = s.p.W8[k * 32 + (lane ^ (k & 31))];
            ull w1 = s.p.W8[(k + 1) * 32 + (lane ^ ((k + 1) & 31))];
            #pragma unroll
            for (int j = 0; j < 16; j++) {
                ulonglong2 ee = *(const ulonglong2*)&s.p.Ed8[((rb + j) << 6) + k];
                acc[j] = ffma2(ee.x, w0, acc[j]);
                acc[j] = ffma2(ee.y, w1, acc[j]);
            }
        }
        __nv_bfloat162* Pb2 = (__nv_bfloat162*)g_P;
        #pragma unroll
        for (int j = 0; j < 16; j++) {
            int r = r0 + rb + j;
            if (r < R) {
                float2 f = unpack2(acc[j]);
                Pb2[r * 32 + lane] = __float22bfloat162_rn(f);
            }
        }
    } else {
        // ---------- User branch: ufg + t2 for 16 users ----------
        const int u0c = (blockIdx.x - nP) * 16;
        #pragma unroll
        for (int e = tid; e < 4096; e += 128) {
            int d = e >> 6, k = e & 63;
            s.u.Wc[k * WCP + d] = fg_user_W[e];
        }
        for (int e = tid; e < 64 * L_; e += 128) {
            int k = e / L_, l = e - k * L_;
            s.u.Wc[k * WCP + 64 + l] = inst_gate_user[e];
        }
        if (tid < 64) s.u.bs[tid] = fg_item_b[tid] + fg_user_b[tid];
        if (tid < 16) {
            int u = u0c + tid;
            s.u.uids[tid] = user_ids[u < B ? u : (B - 1)];
        }
        __syncthreads();
        {
            const float4* ut4 = (const float4*)user_table;
            #pragma unroll
            for (int i = tid; i < 256; i += 128) {
                int uu = i >> 4, c4 = i & 15;
                float4 v = ut4[s.u.uids[uu] * 16 + c4];
                int base = (uu << 6) + (c4 << 2);
                s.u.UEd8[base]     = dup2(v.x);
                s.u.UEd8[base + 1] = dup2(v.y);
                s.u.UEd8[base + 2] = dup2(v.z);
                s.u.UEd8[base + 3] = dup2(v.w);
            }
        }
        __syncthreads();

        const int ub = warp << 2;                     // 4 users per warp
        {   // ufg
            ull acc[4];
            ull binit = *(const ull*)&s.u.bs[lane << 1];
            #pragma unroll
            for (int j = 0; j < 4; j++) acc[j] = binit;
            #pragma unroll 8
            for (int k = 0; k < 64; k++) {
                ull w = *(const ull*)&s.u.Wc[k * WCP + (lane << 1)];
                #pragma unroll
                for (int j = 0; j < 4; j++)
                    acc[j] = ffma2(s.u.UEd8[((ub + j) << 6) + k], w, acc[j]);
            }
            #pragma unroll
            for (int j = 0; j < 4; j++) {
                int u = u0c + ub + j;
                if (u < B) ((ull*)g_ufg)[u * 32 + lane] = acc[j];
            }
        }
        if (lane < 25) {   // t2
            ull acc[4];
            #pragma unroll
            for (int j = 0; j < 4; j++) acc[j] = 0ull;
            #pragma unroll 8
            for (int k = 0; k < 64; k++) {
                ull w = *(const ull*)&s.u.Wc[k * WCP + 64 + (lane << 1)];
                #pragma unroll
                for (int j = 0; j < 4; j++)
                    acc[j] = ffma2(s.u.UEd8[((ub + j) << 6) + k], w, acc[j]);
            }
            #pragma unroll
            for (int j = 0; j < 4; j++) {
                int u = u0c + ub + j;
                if (u < B) *(ull*)&g_t2[u * L_ + (lane << 1)] = acc[j];
            }
        }
    }
}

// ---------------- Main: quarter-warp (8 lanes x 8 dims) per row ----------------
__global__ __launch_bounds__(128) void k_main(
    const int* __restrict__ user_ids,
    const int* __restrict__ item_seq_ids,
    const int* __restrict__ target_item_ids,
    const float* __restrict__ user_table,
    const float* __restrict__ item_table,
    const float* __restrict__ W2_table,
    const float* __restrict__ b2_table,
    const float* __restrict__ inst_gate_item,
    float* __restrict__ out)
{
    __shared__ int   sid[64];
    __shared__ float t2s[64];
    __shared__ float uf[64];
    __shared__ float RU[16 * 64], RS[16 * 64], IS[16];
    __shared__ float v[64];
    __shared__ float s_is;
    __shared__ float outS[104];

    const int b = blockIdx.x;
    const int tid = threadIdx.x;
    const int qw = tid >> 3;             // quarter-warp 0..15
    const int ql = tid & 7;
    const int d8 = ql << 3;              // dims d8..d8+7

    if (tid < 64) {
        int l = tid < L_ ? tid : (L_ - 1);
        sid[tid] = item_seq_ids[b * L_ + l];
        t2s[tid] = g_t2[b * L_ + l];
    } else {
        uf[tid - 64] = g_ufg[b * 64 + (tid - 64)];
    }
    __syncthreads();

    const float4 gi0 = *(const float4*)&inst_gate_item[d8];
    const float4 gi1 = *(const float4*)&inst_gate_item[d8 + 4];
    const float4 uf0 = *(const float4*)&uf[d8];
    const float4 uf1 = *(const float4*)&uf[d8 + 4];

    // ---- l-phase: 4 rounds, row = qw + 16*j, gathers hoisted ----
    int ids_[4]; float t2v[4];
    #pragma unroll
    for (int j = 0; j < 4; j++) { int l = qw + (j << 4); ids_[j] = sid[l]; t2v[j] = t2s[l]; }
    uint4 pr[4]; float4 e0[4], e1[4];
    #pragma unroll
    for (int j = 0; j < 4; j++) pr[j] = *(const uint4*)(g_P + ids_[j] * 64 + d8); // bf16 x8
    #pragma unroll
    for (int j = 0; j < 4; j++) {
        e0[j] = *(const float4*)&item_table[ids_[j] * 64 + d8];
        e1[j] = *(const float4*)&item_table[ids_[j] * 64 + d8 + 4];
    }

    float4 un0 = {0,0,0,0}, un1 = {0,0,0,0}, si0 = {0,0,0,0}, si1 = {0,0,0,0};
    float isum = 0.f;
    #pragma unroll
    for (int j = 0; j < 4; j++) {
        int l = qw + (j << 4);
        float valid = (l < L_) ? 1.f : 0.f;
        const __nv_bfloat162* pb = (const __nv_bfloat162*)&pr[j];
        float2 pa = __bfloat1622float2(pb[0]);
        float2 pbx = __bfloat1622float2(pb[1]);
        float2 pc = __bfloat1622float2(pb[2]);
        float2 pd = __bfloat1622float2(pb[3]);
        float g0 = sigf(pa.x  + uf0.x) * e0[j].x;
        float g1 = sigf(pa.y  + uf0.y) * e0[j].y;
        float g2 = sigf(pbx.x + uf0.z) * e0[j].z;
        float g3 = sigf(pbx.y + uf0.w) * e0[j].w;
        float g4 = sigf(pc.x  + uf1.x) * e1[j].x;
        float g5 = sigf(pc.y  + uf1.y) * e1[j].y;
        float g6 = sigf(pd.x  + uf1.z) * e1[j].z;
        float g7 = sigf(pd.y  + uf1.w) * e1[j].w;
        float t1 = g0*gi0.x + g1*gi0.y + g2*gi0.z + g3*gi0.w
                 + g4*gi1.x + g5*gi1.y + g6*gi1.z + g7*gi1.w;
        t1 += __shfl_xor_sync(0xffffffffu, t1, 4);
        t1 += __shfl_xor_sync(0xffffffffu, t1, 2);
        t1 += __shfl_xor_sync(0xffffffffu, t1, 1);
        float inst = sigf(t1 + t2v[j]) * valid;
        un0.x = fmaf(g0, inst, un0.x); un0.y = fmaf(g1, inst, un0.y);
        un0.z = fmaf(g2, inst, un0.z); un0.w = fmaf(g3, inst, un0.w);
        un1.x = fmaf(g4, inst, un1.x); un1.y = fmaf(g5, inst, un1.y);
        un1.z = fmaf(g6, inst, un1.z); un1.w = fmaf(g7, inst, un1.w);
        si0.x = fmaf(e0[j].x, valid, si0.x); si0.y = fmaf(e0[j].y, valid, si0.y);
        si0.z = fmaf(e0[j].z, valid, si0.z); si0.w = fmaf(e0[j].w, valid, si0.w);
        si1.x = fmaf(e1[j].x, valid, si1.x); si1.y = fmaf(e1[j].y, valid, si1.y);
        si1.z = fmaf(e1[j].z, valid, si1.z); si1.w = fmaf(e1[j].w, valid, si1.w);
        isum += inst;
    }
    *(float4*)&RU[qw * 64 + d8]     = un0;
    *(float4*)&RU[qw * 64 + d8 + 4] = un1;
    *(float4*)&RS[qw * 64 + d8]     = si0;
    *(float4*)&RS[qw * 64 + d8 + 4] = si1;
    if (ql == 0) IS[qw] = isum;
    __syncthreads();

    float av = 0.f, sv = 0.f;
    if (tid < 64) {
        #pragma unroll
        for (int q = 0; q < 16; q++) { av += RU[q * 64 + tid]; sv += RS[q * 64 + tid]; }
    } else if (tid == 64) {
        float q = 0.f;
        #pragma unroll
        for (int i = 0; i < 16; i++) q += IS[i];
        s_is = q;
    }
    __syncthreads();
    if (tid < 64) {
        int uid = user_ids[b];
        v[tid] = user_table[uid * 64 + tid] + __fdividef(av, s_is) + sv;
    }
    __syncthreads();

    // ---- t-phase: 7 rounds (t = qw + 16*j), chunks {4,3} ----
    const float4 v0 = *(const float4*)&v[d8];
    const float4 v1 = *(const float4*)&v[d8 + 4];
    const int* tids = target_item_ids + b * T_;

    #pragma unroll
    for (int c = 0; c < 2; c++) {
        const int j0 = c ? 4 : 0, nj = c ? 3 : 4;
        int wid_[4]; float b2v[4]; float4 w0[4], w1[4];
        #pragma unroll
        for (int j = 0; j < 4; j++) {
            if (j < nj) {
                int t = qw + ((j0 + j) << 4);
                if (t >= T_) t = T_ - 1;
                wid_[j] = tids[t];
            }
        }
        #pragma unroll
        for (int j = 0; j < 4; j++) {
            if (j < nj) {
                w0[j] = *(const float4*)&W2_table[wid_[j] * 64 + d8];
                w1[j] = *(const float4*)&W2_table[wid_[j] * 64 + d8 + 4];
            }
        }
        #pragma unroll
        for (int j = 0; j < 4; j++)
            if (j < nj) b2v[j] = __ldg(&b2_table[wid_[j]]);
        #pragma unroll
        for (int j = 0; j < 4; j++) {
            if (j < nj) {
                float pp = w0[j].x*v0.x + w0[j].y*v0.y + w0[j].z*v0.z + w0[j].w*v0.w
                         + w1[j].x*v1.x + w1[j].y*v1.y + w1[j].z*v1.z + w1[j].w*v1.w;
                pp += __shfl_xor_sync(0xffffffffu, pp, 4);
                pp += __shfl_xor_sync(0xffffffffu, pp, 2);
                pp += __shfl_xor_sync(0xffffffffu, pp, 1);
                int t = qw + ((j0 + j) << 4);
                if (ql == 0 && t < T_) outS[t] = pp + b2v[j];
            }
        }
    }
    __syncthreads();
    if (tid < T_) out[b * T_ + tid] = outS[tid];
}

extern "C" void kernel_launch(void* const* d_in, const int* in_sizes, int n_in,
                              void* d_out, int out_size) {
    const int B = in_sizes[0] > B_MAX ? B_MAX : in_sizes[0];
    int R = in_sizes[4] / D_;
    if (R > I_MAX) R = I_MAX;
    const int nP = (R + 63) / 64;
    const int nU = (B + 15) / 16;

    k_pre<<<nP + nU, 128>>>(
        (const float*)d_in[4], (const float*)d_in[7],
        (const int*)d_in[0], (const float*)d_in[3], (const float*)d_in[9],
        (const float*)d_in[8], (const float*)d_in[10], (const float*)d_in[12],
        R, B, nP);

    k_main<<<B, 128>>>(
        (const int*)d_in[0], (const int*)d_in[1], (const int*)d_in[2],
        (const float*)d_in[3], (const float*)d_in[4], (const float*)d_in[5],
        (const float*)d_in[6], (const float*)d_in[11], (float*)d_out);
}